// round 11
// baseline (speedup 1.0000x reference)
#include <cuda_runtime.h>
#include <cuda_bf16.h>

#define XD 16
#define UD 8
#define AD 32
#define TT 256
#define BSZ 256
#define CH 8

__device__ __align__(256) float gA[XD * XD];
__device__ __align__(256) float gG[XD * XD];
__device__ __align__(256) float gCtNi[XD * AD];
__device__ __align__(256) float gNxD[XD];
__device__ __align__(256) float gE[TT * XD * XD];
__device__ __align__(256) float gF[TT * XD * UD];
__device__ __align__(256) float gK[TT * XD * AD];
__device__ __align__(256) float gGv[TT * BSZ * XD];
__device__ int gTfreeze;

__device__ __forceinline__ float softplusf(float x) {
    return (x > 20.f) ? x : log1pf(expf(x));
}

// ---------------------------------------------------------------- setup -----
__global__ void k_setup(const float* __restrict__ Mm, const float* __restrict__ Nm,
                        const float* __restrict__ dvec, const float* __restrict__ Cm,
                        const float* __restrict__ nx, const float* __restrict__ na)
{
    __shared__ float Qs[256], Us[256], sq[16], si[16], rna[32], T2[256];
    int tid = threadIdx.x;
    int warp = tid >> 5, lane = tid & 31;

    // warp 0: MGS QR of M -> Qs ; warp 1: MGS QR of N -> Us (positive-diag R)
    if (warp < 2 && lane < 16) {
        const float* src = warp ? Nm : Mm;
        float v[16];                       // lane = row; v[j] = column j entry
        #pragma unroll
        for (int j = 0; j < 16; j++) v[j] = src[lane * 16 + j];
        #pragma unroll 1
        for (int j = 0; j < 16; j++) {
            float s = v[j] * v[j];
            #pragma unroll
            for (int o = 8; o > 0; o >>= 1) s += __shfl_xor_sync(0xFFFFu, s, o);
            float invn = rsqrtf(s);
            v[j] *= invn;
            for (int k = j + 1; k < 16; k++) {
                float dt = v[j] * v[k];
                #pragma unroll
                for (int o = 8; o > 0; o >>= 1) dt += __shfl_xor_sync(0xFFFFu, dt, o);
                v[k] -= dt * v[j];
            }
        }
        float* dst = warp ? Us : Qs;
        #pragma unroll
        for (int j = 0; j < 16; j++) dst[lane * 16 + j] = v[j];
    }
    if (tid < 16) {
        float dsp = softplusf(dvec[tid]);
        sq[tid] = sqrtf(dsp);
        si[tid] = rsqrtf(1.0f + dsp);
        gNxD[tid] = softplusf(nx[tid]) + 1e-4f;
    }
    if (tid < 32) rna[tid] = 1.0f / (softplusf(na[tid]) + 1e-4f);
    __syncthreads();

    {   // T2 = diag(sq) Q diag(si) Uq^T
        int k = tid >> 4, j = tid & 15;
        float s = 0.f;
        #pragma unroll
        for (int l = 0; l < 16; l++) s += Qs[k * 16 + l] * si[l] * Us[j * 16 + l];
        T2[tid] = sq[k] * s;
    }
    __syncthreads();
    {   // A = Uq @ T2 ; G = C^T Na^-1 C
        int i = tid >> 4, j = tid & 15;
        float s = 0.f;
        #pragma unroll
        for (int k = 0; k < 16; k++) s += Us[i * 16 + k] * T2[k * 16 + j];
        gA[tid] = s;
        float g = 0.f;
        #pragma unroll
        for (int a2 = 0; a2 < 32; a2++) g += Cm[a2 * 16 + i] * Cm[a2 * 16 + j] * rna[a2];
        gG[tid] = g;
    }
    for (int e = tid; e < 512; e += 256) {
        int i = e >> 5, a2 = e & 31;
        gCtNi[e] = Cm[a2 * 16 + i] * rna[a2];
    }
}

__device__ __forceinline__ void mm16(float* __restrict__ D, const float* __restrict__ Am,
                                     const float* __restrict__ Bm, int tid)
{
    int r0 = tid >> 4, c = tid & 15, r1 = r0 + 8;
    float s0 = 0.f, s1 = 0.f;
    #pragma unroll
    for (int k = 0; k < 16; k++) {
        float bk = Bm[k * 16 + c];
        s0 += Am[r0 * 16 + k] * bk;
        s1 += Am[r1 * 16 + k] * bk;
    }
    D[tid] = s0;
    D[tid + 128] = s1;
}

// ---------------------------------------------- phase 1: shared gain recursion
__global__ void k_phase1(const float* __restrict__ cov0, const float* __restrict__ Bm)
{
    __shared__ float sP[256], sPp[256], sT[256], sM[256], sW[256], sW2[256], sPn[256];
    __shared__ float sA[256], sG[256], sCtNi[512], sB[128], sNx[16];
    __shared__ float redmax[4];
    __shared__ int sConv;

    int tid = threadIdx.x;                 // 128 threads
    int lane = tid & 31, warp = tid >> 5;
    int r0 = tid >> 4, c0 = tid & 15, r1 = r0 + 8;

    sA[tid] = gA[tid];  sA[tid + 128] = gA[tid + 128];
    sG[tid] = gG[tid];  sG[tid + 128] = gG[tid + 128];
    #pragma unroll
    for (int j = 0; j < 4; j++) sCtNi[tid + j * 128] = gCtNi[tid + j * 128];
    sB[tid] = Bm[tid];
    if (tid < 16) sNx[tid] = gNxD[tid];
    sP[tid] = cov0[tid];  sP[tid + 128] = cov0[tid + 128];   // batch 0 (identical all b)
    __syncthreads();

    int tfz = TT - 1;
    for (int t = 0; t < TT; t++) {
        // 1: T = A @ P
        mm16(sT, sA, sP, tid);
        __syncthreads();
        // 2: Pp = T @ A^T + diag(Nx)
        {
            float s0 = 0.f, s1 = 0.f;
            #pragma unroll
            for (int k = 0; k < 16; k++) {
                float ak = sA[c0 * 16 + k];
                s0 += sT[r0 * 16 + k] * ak;
                s1 += sT[r1 * 16 + k] * ak;
            }
            if (r0 == c0) s0 += sNx[r0];
            if (r1 == c0) s1 += sNx[r1];
            sPp[tid] = s0; sPp[tid + 128] = s1;
        }
        __syncthreads();
        // 3: M = I + Pp @ G
        {
            float s0 = 0.f, s1 = 0.f;
            #pragma unroll
            for (int k = 0; k < 16; k++) {
                float gk = sG[k * 16 + c0];
                s0 += sPp[r0 * 16 + k] * gk;
                s1 += sPp[r1 * 16 + k] * gk;
            }
            if (r0 == c0) s0 += 1.0f;
            if (r1 == c0) s1 += 1.0f;
            sM[tid] = s0; sM[tid + 128] = s1;
        }
        __syncthreads();
        // 4: W = inv(M), in-place Gauss-Jordan, lane = column
        if (tid < 16) {
            float m[16];
            #pragma unroll
            for (int i = 0; i < 16; i++) m[i] = sM[i * 16 + tid];
            #pragma unroll 1
            for (int k = 0; k < 16; k++) {
                float ipiv = 1.0f / __shfl_sync(0xFFFFu, m[k], k);
                float rk = ((tid == k) ? 1.0f : m[k]) * ipiv;
                m[k] = rk;
                #pragma unroll
                for (int i = 0; i < 16; i++) {
                    float fi = __shfl_sync(0xFFFFu, m[i], k);
                    if (i != k) {
                        float base = (tid == k) ? 0.0f : m[i];
                        m[i] = base - fi * rk;
                    }
                }
            }
            #pragma unroll
            for (int i = 0; i < 16; i++) sW[i * 16 + tid] = m[i];
        }
        __syncthreads();
        // 5: T = M @ W (Newton residual)
        mm16(sT, sM, sW, tid);
        __syncthreads();
        // 6: W2 = 2W - W @ T
        {
            float s0 = 0.f, s1 = 0.f;
            #pragma unroll
            for (int k = 0; k < 16; k++) {
                float tk = sT[k * 16 + c0];
                s0 += sW[r0 * 16 + k] * tk;
                s1 += sW[r1 * 16 + k] * tk;
            }
            sW2[tid] = 2.0f * sW[r0 * 16 + c0] - s0;
            sW2[tid + 128] = 2.0f * sW[r1 * 16 + c0] - s1;
        }
        __syncthreads();
        // 7: Pn = W2 @ Pp ; E = W2 @ A ; F = W2 @ B
        {
            float p0 = 0.f, p1 = 0.f, e0 = 0.f, e1 = 0.f;
            #pragma unroll
            for (int k = 0; k < 16; k++) {
                float w0 = sW2[r0 * 16 + k], w1 = sW2[r1 * 16 + k];
                float pk = sPp[k * 16 + c0], ak = sA[k * 16 + c0];
                p0 += w0 * pk; p1 += w1 * pk;
                e0 += w0 * ak; e1 += w1 * ak;
            }
            sPn[tid] = p0; sPn[tid + 128] = p1;
            gE[t * 256 + tid] = e0; gE[t * 256 + tid + 128] = e1;
            int r = tid >> 3, cu = tid & 7;
            float s = 0.f;
            #pragma unroll
            for (int k = 0; k < 16; k++) s += sW2[r * 16 + k] * sB[k * 8 + cu];
            gF[t * 128 + tid] = s;
        }
        __syncthreads();
        // 8: K = Pn @ CtNi ; convergence ; P <- Pn
        {
            float dmax = fmaxf(fabsf(sPn[tid] - sP[tid]),
                               fabsf(sPn[tid + 128] - sP[tid + 128]));
            #pragma unroll
            for (int j = 0; j < 4; j++) {
                int e = tid + j * 128;
                int r = e >> 5, ca = e & 31;
                float s = 0.f;
                #pragma unroll
                for (int k = 0; k < 16; k++) s += sPn[r * 16 + k] * sCtNi[k * 32 + ca];
                gK[t * 512 + e] = s;
            }
            #pragma unroll
            for (int o = 16; o > 0; o >>= 1)
                dmax = fmaxf(dmax, __shfl_xor_sync(0xFFFFFFFFu, dmax, o));
            if (lane == 0) redmax[warp] = dmax;
            sP[tid] = sPn[tid];
            sP[tid + 128] = sPn[tid + 128];
        }
        __syncthreads();
        if (tid == 0) {
            float m = fmaxf(fmaxf(redmax[0], redmax[1]), fmaxf(redmax[2], redmax[3]));
            sConv = (m < 1e-7f) ? 1 : 0;
        }
        __syncthreads();
        if (sConv) { tfz = t; break; }
    }
    if (tid == 0) gTfreeze = tfz;
}

// -------------------------------------- phase 2: g[t,b] = F_t u + K_t a -----
__global__ void k_phase2(const float* __restrict__ u, const float* __restrict__ a)
{
    __shared__ float sF[128], sK[512], su[128], sa[512];
    __shared__ int stf;
    int tid = threadIdx.x;
    int t = blockIdx.y;
    int bbase = blockIdx.x * 16;
    if (tid == 0) stf = gTfreeze;
    __syncthreads();
    int ts = (t < stf) ? t : stf;

    if (tid < 128) sF[tid] = gF[ts * 128 + tid];
    sK[tid] = gK[ts * 512 + tid];
    sK[tid + 256] = gK[ts * 512 + 256 + tid];
    if (tid < 128) {
        int i = tid >> 3, j = tid & 7;
        su[tid] = u[(bbase + i) * (TT * UD) + t * UD + j];
    }
    {
        int i = tid >> 5, j = tid & 31;
        sa[tid] = a[(bbase + i) * (TT * AD) + t * AD + j];
        int e = tid + 256;
        i = e >> 5; j = e & 31;
        sa[e] = a[(bbase + i) * (TT * AD) + t * AD + j];
    }
    __syncthreads();

    int bl = tid >> 4, x = tid & 15;
    float s = 0.f;
    #pragma unroll
    for (int j = 0; j < 8; j++) s += sF[x * 8 + j] * su[bl * 8 + j];
    #pragma unroll
    for (int j = 0; j < 32; j++) s += sK[x * 32 + j] * sa[bl * 32 + j];
    gGv[(t * BSZ + bbase + bl) * 16 + x] = s;
}

// ------------------------------ phase 3: mean <- E_t mean + g, serial in t --
__global__ void k_phase3(const float* __restrict__ mean0, float* __restrict__ out)
{
    __shared__ __align__(16) float sb[2][CH * 512];
    __shared__ int stf;
    int tid = threadIdx.x;                 // 256 threads
    int lane = tid & 31, w = tid >> 5;
    int bbase = blockIdx.x * 16;
    int x = lane & 15;
    int bl = 2 * w + (lane >> 4);
    int b = bbase + bl;

    if (tid == 0) stf = gTfreeze;
    __syncthreads();
    int tf = stf;

    float mv = mean0[b * 16 + x];

    // load chunk 0
    #pragma unroll
    for (int j = 0; j < 4; j++) {
        int idx4 = tid + j * 256;
        int s = idx4 >> 7, wi = idx4 & 127;
        int t = s;
        int ts = (t < tf) ? t : tf;
        float4 v;
        if (wi < 64) v = ((const float4*)(gE + ts * 256))[wi];
        else         v = ((const float4*)(gGv + (t * BSZ + bbase) * 16))[wi - 64];
        ((float4*)sb[0])[idx4] = v;
    }
    __syncthreads();

    for (int c = 0; c < TT / CH; c++) {
        int cur = c & 1;
        float4 pre[4];
        bool hasNext = (c + 1 < TT / CH);
        if (hasNext) {
            #pragma unroll
            for (int j = 0; j < 4; j++) {
                int idx4 = tid + j * 256;
                int s = idx4 >> 7, wi = idx4 & 127;
                int t = (c + 1) * CH + s;
                int ts = (t < tf) ? t : tf;
                if (wi < 64) pre[j] = ((const float4*)(gE + ts * 256))[wi];
                else         pre[j] = ((const float4*)(gGv + (t * BSZ + bbase) * 16))[wi - 64];
            }
        }
        #pragma unroll
        for (int s = 0; s < CH; s++) {
            const float* base = &sb[cur][s * 512];
            const float4* ep = (const float4*)(base + x * 16);
            float4 q0 = ep[0], q1 = ep[1], q2 = ep[2], q3 = ep[3];
            float er[16];
            er[0]=q0.x; er[1]=q0.y; er[2]=q0.z; er[3]=q0.w;
            er[4]=q1.x; er[5]=q1.y; er[6]=q1.z; er[7]=q1.w;
            er[8]=q2.x; er[9]=q2.y; er[10]=q2.z; er[11]=q2.w;
            er[12]=q3.x; er[13]=q3.y; er[14]=q3.z; er[15]=q3.w;
            float a0 = base[256 + bl * 16 + x], a1 = 0.f;
            #pragma unroll
            for (int k = 0; k < 16; k++) {
                float mk = __shfl_sync(0xFFFFFFFFu, mv, k, 16);
                if (k & 1) a1 += er[k] * mk;
                else       a0 += er[k] * mk;
            }
            mv = a0 + a1;
            int t = c * CH + s;
            out[b * (TT * XD) + t * 16 + x] = mv;
        }
        if (hasNext) {
            #pragma unroll
            for (int j = 0; j < 4; j++)
                ((float4*)sb[cur ^ 1])[tid + j * 256] = pre[j];
        }
        __syncthreads();
    }
}

extern "C" void kernel_launch(void* const* d_in, const int* in_sizes, int n_in,
                              void* d_out, int out_size)
{
    const float* mean0 = (const float*)d_in[0];
    const float* cov0  = (const float*)d_in[1];
    const float* u     = (const float*)d_in[2];
    const float* a     = (const float*)d_in[3];
    const float* Mm    = (const float*)d_in[4];
    const float* Nm    = (const float*)d_in[5];
    const float* dvec  = (const float*)d_in[6];
    const float* Bm    = (const float*)d_in[7];
    const float* Cm    = (const float*)d_in[8];
    const float* nx    = (const float*)d_in[9];
    const float* na    = (const float*)d_in[10];
    float* out = (float*)d_out;

    k_setup<<<1, 256>>>(Mm, Nm, dvec, Cm, nx, na);
    k_phase1<<<1, 128>>>(cov0, Bm);
    dim3 g2(16, 256);
    k_phase2<<<g2, 256>>>(u, a);
    k_phase3<<<16, 256>>>(mean0, out);
}

// round 14
// speedup vs baseline: 1.3366x; 1.3366x over previous
#include <cuda_runtime.h>
#include <cuda_bf16.h>

#define XD 16
#define UD 8
#define AD 32
#define TT 256
#define BSZ 256

__device__ __align__(256) float gA[XD * XD];
__device__ __align__(256) float gG[XD * XD];
__device__ __align__(256) float gCtNi[XD * AD];
__device__ __align__(256) float gNxD[XD];
__device__ __align__(256) float gE[TT * XD * XD];
__device__ __align__(256) float gF[TT * XD * UD];
__device__ __align__(256) float gK[TT * XD * AD];
__device__ __align__(256) float gGv[TT * BSZ * XD];
__device__ __align__(256) float gPhi[TT * 2 * 256];   // P1, P2 per t
__device__ __align__(256) float gH[TT * 256];         // P3 (or P_min(t,3))
__device__ __align__(256) float gG4[TT * BSZ * XD];
__device__ int gTfreeze;

__device__ __forceinline__ float softplusf(float x) {
    return (x > 20.f) ? x : log1pf(expf(x));
}

// ---------------------------------------------------------------- setup -----
__global__ void k_setup(const float* __restrict__ Mm, const float* __restrict__ Nm,
                        const float* __restrict__ dvec, const float* __restrict__ Cm,
                        const float* __restrict__ nx, const float* __restrict__ na)
{
    __shared__ float Qs[256], Us[256], sq[16], si[16], rna[32], T2[256];
    int tid = threadIdx.x;
    int warp = tid >> 5, lane = tid & 31;

    if (warp < 2 && lane < 16) {               // warp-MGS QR: positive-diag R
        const float* src = warp ? Nm : Mm;
        float v[16];
        #pragma unroll
        for (int j = 0; j < 16; j++) v[j] = src[lane * 16 + j];
        #pragma unroll 1
        for (int j = 0; j < 16; j++) {
            float s = v[j] * v[j];
            #pragma unroll
            for (int o = 8; o > 0; o >>= 1) s += __shfl_xor_sync(0xFFFFu, s, o);
            float invn = rsqrtf(s);
            v[j] *= invn;
            for (int k = j + 1; k < 16; k++) {
                float dt = v[j] * v[k];
                #pragma unroll
                for (int o = 8; o > 0; o >>= 1) dt += __shfl_xor_sync(0xFFFFu, dt, o);
                v[k] -= dt * v[j];
            }
        }
        float* dst = warp ? Us : Qs;
        #pragma unroll
        for (int j = 0; j < 16; j++) dst[lane * 16 + j] = v[j];
    }
    if (tid < 16) {
        float dsp = softplusf(dvec[tid]);
        sq[tid] = sqrtf(dsp);
        si[tid] = rsqrtf(1.0f + dsp);
        gNxD[tid] = softplusf(nx[tid]) + 1e-4f;
    }
    if (tid < 32) rna[tid] = 1.0f / (softplusf(na[tid]) + 1e-4f);
    __syncthreads();

    {
        int k = tid >> 4, j = tid & 15;
        float s = 0.f;
        #pragma unroll
        for (int l = 0; l < 16; l++) s += Qs[k * 16 + l] * si[l] * Us[j * 16 + l];
        T2[tid] = sq[k] * s;
    }
    __syncthreads();
    {
        int i = tid >> 4, j = tid & 15;
        float s = 0.f;
        #pragma unroll
        for (int k = 0; k < 16; k++) s += Us[i * 16 + k] * T2[k * 16 + j];
        gA[tid] = s;
        float g = 0.f;
        #pragma unroll
        for (int a2 = 0; a2 < 32; a2++) g += Cm[a2 * 16 + i] * Cm[a2 * 16 + j] * rna[a2];
        gG[tid] = g;
    }
    for (int e = tid; e < 512; e += 256) {
        int i = e >> 5, a2 = e & 31;
        gCtNi[e] = Cm[a2 * 16 + i] * rna[a2];
    }
}

// ------------------------------- phase 1: shared Riccati / gain recursion ---
__global__ void k_phase1(const float* __restrict__ cov0, const float* __restrict__ Bm)
{
    __shared__ float sP[256], sPp[256], sT[256], sM[256], sW[256];
    __shared__ float sA[256], sAT[256], sG[256], sCtNi[512], sY[512], sB[128], sNx[16];
    __shared__ float redmax[8];

    int tid = threadIdx.x;                  // 256 threads
    int r = tid >> 4, c = tid & 15;
    int lane = tid & 31, warp = tid >> 5;

    float av = gA[tid];
    sA[tid] = av;
    sAT[c * 16 + r] = av;                   // sAT[k*16+c] == A[c][k]
    sG[tid] = gG[tid];
    sCtNi[tid] = gCtNi[tid];
    sCtNi[tid + 256] = gCtNi[tid + 256];
    if (tid < 128) sB[tid] = Bm[tid];
    if (tid < 16) sNx[tid] = gNxD[tid];
    sP[tid] = cov0[tid];                    // batch 0 (identical across b)
    __syncthreads();

    int tfz = TT - 1;
    for (int t = 0; t < TT; t++) {
        // A: T = A @ P
        {
            float s = 0.f;
            #pragma unroll
            for (int k = 0; k < 16; k++) s += sA[r * 16 + k] * sP[k * 16 + c];
            sT[tid] = s;
        }
        __syncthreads();
        // B: Pp = T @ A^T + diag(Nx)
        {
            float s = 0.f;
            #pragma unroll
            for (int k = 0; k < 16; k++) s += sT[r * 16 + k] * sAT[k * 16 + c];
            if (r == c) s += sNx[r];
            sPp[tid] = s;
        }
        __syncthreads();
        // C: M = I + Pp @ G ;  Y = Pp @ CtNi
        {
            float s = 0.f;
            #pragma unroll
            for (int k = 0; k < 16; k++) s += sPp[r * 16 + k] * sG[k * 16 + c];
            if (r == c) s += 1.0f;
            sM[tid] = s;
            #pragma unroll
            for (int j = 0; j < 2; j++) {
                int e = tid + j * 256;
                int ry = e >> 5, ca = e & 31;
                float y = 0.f;
                #pragma unroll
                for (int k = 0; k < 16; k++) y += sPp[ry * 16 + k] * sCtNi[k * 32 + ca];
                sY[e] = y;
            }
        }
        __syncthreads();
        // D: W = inv(M), warp-register Gauss-Jordan (lanes 0..15, lane = column)
        if (tid < 16) {
            float m[16];
            #pragma unroll
            for (int i = 0; i < 16; i++) m[i] = sM[i * 16 + tid];
            #pragma unroll 1
            for (int k = 0; k < 16; k++) {
                float ipiv = 1.0f / __shfl_sync(0xFFFFu, m[k], k);
                float rk = ((tid == k) ? 1.0f : m[k]) * ipiv;
                m[k] = rk;
                #pragma unroll
                for (int i = 0; i < 16; i++) {
                    float fi = __shfl_sync(0xFFFFu, m[i], k);
                    if (i != k) {
                        float base = (tid == k) ? 0.0f : m[i];
                        m[i] = base - fi * rk;
                    }
                }
            }
            #pragma unroll
            for (int i = 0; i < 16; i++) sW[i * 16 + tid] = m[i];
        }
        __syncthreads();
        // E: Pn = W@Pp ; E = W@A ; F = W@B ; K = W@Y ; delta
        {
            float pn = 0.f, ee = 0.f;
            #pragma unroll
            for (int k = 0; k < 16; k++) {
                float w = sW[r * 16 + k];
                pn += w * sPp[k * 16 + c];
                ee += w * sA[k * 16 + c];
            }
            gE[t * 256 + tid] = ee;
            if (tid < 128) {
                int rf = tid >> 3, cu = tid & 7;
                float f = 0.f;
                #pragma unroll
                for (int k = 0; k < 16; k++) f += sW[rf * 16 + k] * sB[k * 8 + cu];
                gF[t * 128 + tid] = f;
            }
            #pragma unroll
            for (int j = 0; j < 2; j++) {
                int e = tid + j * 256;
                int rk2 = e >> 5, ca = e & 31;
                float kk = 0.f;
                #pragma unroll
                for (int k = 0; k < 16; k++) kk += sW[rk2 * 16 + k] * sY[k * 32 + ca];
                gK[t * 512 + e] = kk;
            }
            float d = fabsf(pn - sP[tid]);
            sP[tid] = pn;
            #pragma unroll
            for (int o = 16; o > 0; o >>= 1)
                d = fmaxf(d, __shfl_xor_sync(0xFFFFFFFFu, d, o));
            if (lane == 0) redmax[warp] = d;
        }
        __syncthreads();
        {
            float m = redmax[0];
            #pragma unroll
            for (int w2 = 1; w2 < 8; w2++) m = fmaxf(m, redmax[w2]);
            if (m < 1e-7f) { tfz = t; break; }
        }
    }
    if (tid == 0) gTfreeze = tfz;
}

// -------------------------------------- phase 2: g[t,b] = F_t u + K_t a -----
__global__ void k_phase2(const float* __restrict__ u, const float* __restrict__ a)
{
    __shared__ float sF[128], sK[512], su[128], sa[512];
    __shared__ int stf;
    int tid = threadIdx.x;
    int t = blockIdx.y;
    int bbase = blockIdx.x * 16;
    if (tid == 0) stf = gTfreeze;
    __syncthreads();
    int ts = (t < stf) ? t : stf;

    if (tid < 128) sF[tid] = gF[ts * 128 + tid];
    sK[tid] = gK[ts * 512 + tid];
    sK[tid + 256] = gK[ts * 512 + 256 + tid];
    if (tid < 128) {
        int i = tid >> 3, j = tid & 7;
        su[tid] = u[(bbase + i) * (TT * UD) + t * UD + j];
    }
    {
        int i = tid >> 5, j = tid & 31;
        sa[tid] = a[(bbase + i) * (TT * AD) + t * AD + j];
        int e = tid + 256;
        i = e >> 5; j = e & 31;
        sa[e] = a[(bbase + i) * (TT * AD) + t * AD + j];
    }
    __syncthreads();

    int bl = tid >> 4, x = tid & 15;
    float s = 0.f;
    #pragma unroll
    for (int j = 0; j < 8; j++) s += sF[x * 8 + j] * su[bl * 8 + j];
    #pragma unroll
    for (int j = 0; j < 32; j++) s += sK[x * 32 + j] * sa[bl * 32 + j];
    gGv[(t * BSZ + bbase + bl) * 16 + x] = s;
}

// ---------------- stride-4 transfer matrices: P1,P2 -> gPhi ; P3 -> gH ------
__global__ void k_prod()
{
    __shared__ float sCur[256], sNext[256];
    __shared__ int stf;
    int t = blockIdx.x, tid = threadIdx.x;
    int r = tid >> 4, c = tid & 15;
    if (tid == 0) stf = gTfreeze;
    __syncthreads();
    int tf = stf;

    sCur[tid] = gE[((t < tf) ? t : tf) * 256 + tid];
    #pragma unroll 1
    for (int j = 1; j <= 3; j++) {
        int s = t - j;
        if (s >= 0) sNext[tid] = gE[((s < tf) ? s : tf) * 256 + tid];
        __syncthreads();
        float v;
        if (s >= 0) {
            v = 0.f;
            #pragma unroll
            for (int k = 0; k < 16; k++) v += sCur[r * 16 + k] * sNext[k * 16 + c];
        } else {
            v = sCur[tid];
        }
        __syncthreads();
        sCur[tid] = v;
        if (j == 1)      gPhi[t * 512 + tid] = v;
        else if (j == 2) gPhi[t * 512 + 256 + tid] = v;
        else             gH[t * 256 + tid] = v;
    }
}

// ------ G4_t = g_t + P0 g_{t-1} + P1 g_{t-2} + P2 g_{t-3} (P0 = E_t) --------
__global__ void k_g4()
{
    __shared__ float sP0t[256], sP1t[256], sP2t[256], sg[1024];
    __shared__ int stf;
    int tid = threadIdx.x;
    int t = blockIdx.y;
    int bbase = blockIdx.x * 16;
    int r = tid >> 4, c = tid & 15;
    if (tid == 0) stf = gTfreeze;
    __syncthreads();
    int tf = stf;

    sP0t[c * 16 + r] = gE[((t < tf) ? t : tf) * 256 + tid];
    sP1t[c * 16 + r] = gPhi[t * 512 + tid];
    sP2t[c * 16 + r] = gPhi[t * 512 + 256 + tid];
    #pragma unroll
    for (int j = 0; j < 4; j++) {
        int s = t - j;
        sg[j * 256 + tid] = (s >= 0) ? gGv[(s * BSZ + bbase) * 16 + tid] : 0.f;
    }
    __syncthreads();

    int bl = tid >> 4, x = tid & 15;
    float v = sg[bl * 16 + x];
    #pragma unroll
    for (int k = 0; k < 16; k++) v += sP0t[k * 16 + x] * sg[256 + bl * 16 + k];
    #pragma unroll
    for (int k = 0; k < 16; k++) v += sP1t[k * 16 + x] * sg[512 + bl * 16 + k];
    #pragma unroll
    for (int k = 0; k < 16; k++) v += sP2t[k * 16 + x] * sg[768 + bl * 16 + k];
    gG4[(t * BSZ + bbase) * 16 + tid] = v;
}

// ----------- chain: mean_t = H_t mean_{t-4} + G4_t, 4 sub-chains/batch ------
__global__ void k_chain(const float* __restrict__ mean0, float* __restrict__ out)
{
    int tid = threadIdx.x;                  // 256 threads: 16 chains (16 batches, 1 residue)
    int lane = tid & 31, w = tid >> 5;
    int res = blockIdx.x & 3;
    int bbase = (blockIdx.x >> 2) * 16;
    int x = lane & 15;
    int bl = 2 * w + (lane >> 4);
    int b = bbase + bl;

    float mv = mean0[b * 16 + x];

    int t = res;
    const float4* hp = (const float4*)(gH + t * 256 + x * 16);
    float4 h0 = hp[0], h1 = hp[1], h2 = hp[2], h3 = hp[3];
    float gg = gG4[(t * BSZ + b) * 16 + x];

    #pragma unroll 1
    for (int i = 0; i < TT / 4; i++) {
        int tn = t + 4;
        float4 n0, n1, n2, n3; float gn;
        if (tn < TT) {
            const float4* np = (const float4*)(gH + tn * 256 + x * 16);
            n0 = np[0]; n1 = np[1]; n2 = np[2]; n3 = np[3];
            gn = gG4[(tn * BSZ + b) * 16 + x];
        }
        float a0 = gg, a1 = 0.f, a2 = 0.f, a3 = 0.f;
        float hr[16];
        hr[0]=h0.x; hr[1]=h0.y; hr[2]=h0.z; hr[3]=h0.w;
        hr[4]=h1.x; hr[5]=h1.y; hr[6]=h1.z; hr[7]=h1.w;
        hr[8]=h2.x; hr[9]=h2.y; hr[10]=h2.z; hr[11]=h2.w;
        hr[12]=h3.x; hr[13]=h3.y; hr[14]=h3.z; hr[15]=h3.w;
        #pragma unroll
        for (int k = 0; k < 16; k++) {
            float mk = __shfl_sync(0xFFFFFFFFu, mv, k, 16);
            if ((k & 3) == 0)      a0 += hr[k] * mk;
            else if ((k & 3) == 1) a1 += hr[k] * mk;
            else if ((k & 3) == 2) a2 += hr[k] * mk;
            else                   a3 += hr[k] * mk;
        }
        mv = (a0 + a1) + (a2 + a3);
        out[b * (TT * XD) + t * 16 + x] = mv;
        if (tn < TT) { h0 = n0; h1 = n1; h2 = n2; h3 = n3; gg = gn; t = tn; }
    }
}

extern "C" void kernel_launch(void* const* d_in, const int* in_sizes, int n_in,
                              void* d_out, int out_size)
{
    const float* mean0 = (const float*)d_in[0];
    const float* cov0  = (const float*)d_in[1];
    const float* u     = (const float*)d_in[2];
    const float* a     = (const float*)d_in[3];
    const float* Mm    = (const float*)d_in[4];
    const float* Nm    = (const float*)d_in[5];
    const float* dvec  = (const float*)d_in[6];
    const float* Bm    = (const float*)d_in[7];
    const float* Cm    = (const float*)d_in[8];
    const float* nx    = (const float*)d_in[9];
    const float* na    = (const float*)d_in[10];
    float* out = (float*)d_out;

    k_setup<<<1, 256>>>(Mm, Nm, dvec, Cm, nx, na);
    k_phase1<<<1, 256>>>(cov0, Bm);
    dim3 g2(16, 256);
    k_phase2<<<g2, 256>>>(u, a);
    k_prod<<<256, 256>>>();
    k_g4<<<g2, 256>>>();
    k_chain<<<64, 256>>>(mean0, out);
}

// round 16
// speedup vs baseline: 1.4027x; 1.0494x over previous
#include <cuda_runtime.h>
#include <cuda_bf16.h>

#define XD 16
#define UD 8
#define AD 32
#define TT 256
#define BSZ 256
#define FREEZE_TH 1e-5f

__device__ __align__(256) float gE[TT * XD * XD];
__device__ __align__(256) float gF[TT * XD * UD];
__device__ __align__(256) float gK[TT * XD * AD];
__device__ __align__(256) float gGv[TT * BSZ * XD];
__device__ __align__(256) float gPhi[TT * 2 * 256];   // P1, P2 per t
__device__ __align__(256) float gH[TT * 256];         // P3
__device__ __align__(256) float gG4[TT * BSZ * XD];
__device__ int gTfreeze;

__device__ __forceinline__ float softplusf(float x) {
    return (x > 20.f) ? x : log1pf(expf(x));
}

// ============== phase 1 (fused setup + shared Riccati/gain recursion) =======
__global__ void k_phase1(const float* __restrict__ cov0, const float* __restrict__ Bm,
                         const float* __restrict__ Mm, const float* __restrict__ Nm,
                         const float* __restrict__ dvec, const float* __restrict__ Cm,
                         const float* __restrict__ nx, const float* __restrict__ na)
{
    __shared__ float Qs[256], Us[256], T2[256], sq[16], si[16], rna[32];
    __shared__ float sP[256], sPp[256], sT[256], sM[256], sW[256];
    __shared__ float sA[256], sAT[256], sG[256], sCtNi[512], sY[512], sB[128], sNx[16];
    __shared__ float redmax[8];

    int tid = threadIdx.x;                  // 256 threads
    int r = tid >> 4, c = tid & 15;
    int lane = tid & 31, warp = tid >> 5;

    // ---- setup: MGS QR (positive-diag R == reference sign-fix) ----
    if (warp < 2 && lane < 16) {
        const float* src = warp ? Nm : Mm;
        float v[16];
        #pragma unroll
        for (int j = 0; j < 16; j++) v[j] = src[lane * 16 + j];
        #pragma unroll 1
        for (int j = 0; j < 16; j++) {
            float s = v[j] * v[j];
            #pragma unroll
            for (int o = 8; o > 0; o >>= 1) s += __shfl_xor_sync(0xFFFFu, s, o);
            float invn = rsqrtf(s);
            v[j] *= invn;
            for (int k = j + 1; k < 16; k++) {
                float dt = v[j] * v[k];
                #pragma unroll
                for (int o = 8; o > 0; o >>= 1) dt += __shfl_xor_sync(0xFFFFu, dt, o);
                v[k] -= dt * v[j];
            }
        }
        float* dst = warp ? Us : Qs;
        #pragma unroll
        for (int j = 0; j < 16; j++) dst[lane * 16 + j] = v[j];
    }
    if (tid < 16) {
        float dsp = softplusf(dvec[tid]);
        sq[tid] = sqrtf(dsp);
        si[tid] = rsqrtf(1.0f + dsp);
        sNx[tid] = softplusf(nx[tid]) + 1e-4f;
    }
    if (tid < 32) rna[tid] = 1.0f / (softplusf(na[tid]) + 1e-4f);
    if (tid < 128) sB[tid] = Bm[tid];
    sP[tid] = cov0[tid];                    // batch 0 (identical across b)
    __syncthreads();

    {   // T2 = diag(sq) Q diag(si) Uq^T
        int k = tid >> 4, j = tid & 15;
        float s = 0.f;
        #pragma unroll
        for (int l = 0; l < 16; l++) s += Qs[k * 16 + l] * si[l] * Us[j * 16 + l];
        T2[tid] = sq[k] * s;
    }
    __syncthreads();
    {   // A = Uq @ T2 ; G = C^T Na^-1 C ; CtNi
        float s = 0.f;
        #pragma unroll
        for (int k = 0; k < 16; k++) s += Us[r * 16 + k] * T2[k * 16 + c];
        sA[tid] = s;
        sAT[c * 16 + r] = s;
        float g = 0.f;
        #pragma unroll
        for (int a2 = 0; a2 < 32; a2++) g += Cm[a2 * 16 + r] * Cm[a2 * 16 + c] * rna[a2];
        sG[tid] = g;
        #pragma unroll
        for (int j = 0; j < 2; j++) {
            int e = tid + j * 256;
            int i = e >> 5, a2 = e & 31;
            sCtNi[e] = Cm[a2 * 16 + i] * rna[a2];
        }
    }
    __syncthreads();

    // ---- Riccati recursion ----
    int tfz = TT - 1;
    for (int t = 0; t < TT; t++) {
        // A: T = A @ P
        {
            float s = 0.f;
            #pragma unroll
            for (int k = 0; k < 16; k++) s += sA[r * 16 + k] * sP[k * 16 + c];
            sT[tid] = s;
        }
        __syncthreads();
        // B: Pp = T @ A^T + diag(Nx)
        {
            float s = 0.f;
            #pragma unroll
            for (int k = 0; k < 16; k++) s += sT[r * 16 + k] * sAT[k * 16 + c];
            if (r == c) s += sNx[r];
            sPp[tid] = s;
        }
        __syncthreads();
        // C: M = I + Pp @ G ; Y = Pp @ CtNi
        {
            float s = 0.f;
            #pragma unroll
            for (int k = 0; k < 16; k++) s += sPp[r * 16 + k] * sG[k * 16 + c];
            if (r == c) s += 1.0f;
            sM[tid] = s;
            #pragma unroll
            for (int j = 0; j < 2; j++) {
                int e = tid + j * 256;
                int ry = e >> 5, ca = e & 31;
                float y = 0.f;
                #pragma unroll
                for (int k = 0; k < 16; k++) y += sPp[ry * 16 + k] * sCtNi[k * 32 + ca];
                sY[e] = y;
            }
        }
        __syncthreads();
        // D: W = inv(M), warp-register Gauss-Jordan (lane = column)
        if (tid < 16) {
            float m[16];
            #pragma unroll
            for (int i = 0; i < 16; i++) m[i] = sM[i * 16 + tid];
            #pragma unroll 1
            for (int k = 0; k < 16; k++) {
                float ipiv = 1.0f / __shfl_sync(0xFFFFu, m[k], k);
                float rk = ((tid == k) ? 1.0f : m[k]) * ipiv;
                m[k] = rk;
                #pragma unroll
                for (int i = 0; i < 16; i++) {
                    float fi = __shfl_sync(0xFFFFu, m[i], k);
                    if (i != k) {
                        float base = (tid == k) ? 0.0f : m[i];
                        m[i] = base - fi * rk;
                    }
                }
            }
            #pragma unroll
            for (int i = 0; i < 16; i++) sW[i * 16 + tid] = m[i];
        }
        __syncthreads();
        // E: Pn = W@Pp ; E = W@A ; F = W@B ; K = W@Y ; delta
        {
            float pn = 0.f, ee = 0.f;
            #pragma unroll
            for (int k = 0; k < 16; k++) {
                float w = sW[r * 16 + k];
                pn += w * sPp[k * 16 + c];
                ee += w * sA[k * 16 + c];
            }
            gE[t * 256 + tid] = ee;
            if (tid < 128) {
                int rf = tid >> 3, cu = tid & 7;
                float f = 0.f;
                #pragma unroll
                for (int k = 0; k < 16; k++) f += sW[rf * 16 + k] * sB[k * 8 + cu];
                gF[t * 128 + tid] = f;
            }
            #pragma unroll
            for (int j = 0; j < 2; j++) {
                int e = tid + j * 256;
                int rk2 = e >> 5, ca = e & 31;
                float kk = 0.f;
                #pragma unroll
                for (int k = 0; k < 16; k++) kk += sW[rk2 * 16 + k] * sY[k * 32 + ca];
                gK[t * 512 + e] = kk;
            }
            float d = fabsf(pn - sP[tid]);
            sP[tid] = pn;
            #pragma unroll
            for (int o = 16; o > 0; o >>= 1)
                d = fmaxf(d, __shfl_xor_sync(0xFFFFFFFFu, d, o));
            if (lane == 0) redmax[warp] = d;
        }
        __syncthreads();
        {
            float m = redmax[0];
            #pragma unroll
            for (int w2 = 1; w2 < 8; w2++) m = fmaxf(m, redmax[w2]);
            if (m < FREEZE_TH) { tfz = t; break; }
        }
    }
    if (tid == 0) gTfreeze = tfz;
}

// ====== phase 2 (g[t,b] = F_t u + K_t a) fused with stride-4 products =======
__global__ void k_phase2(const float* __restrict__ u, const float* __restrict__ a)
{
    __shared__ float sF[128], sK[512], su[128], sa[512];
    __shared__ float sCur[256], sNext[256];
    __shared__ int stf;
    int tid = threadIdx.x;
    int t = blockIdx.y;
    if (tid == 0) stf = gTfreeze;
    __syncthreads();
    int tf = stf;

    if (blockIdx.x == 16) {
        // ---- transfer-matrix products: P1,P2 -> gPhi ; P3 -> gH ----
        int r = tid >> 4, c = tid & 15;
        sCur[tid] = gE[((t < tf) ? t : tf) * 256 + tid];
        #pragma unroll 1
        for (int j = 1; j <= 3; j++) {
            int s = t - j;
            if (s >= 0) sNext[tid] = gE[((s < tf) ? s : tf) * 256 + tid];
            __syncthreads();
            float v;
            if (s >= 0) {
                v = 0.f;
                #pragma unroll
                for (int k = 0; k < 16; k++) v += sCur[r * 16 + k] * sNext[k * 16 + c];
            } else {
                v = sCur[tid];
            }
            __syncthreads();
            sCur[tid] = v;
            if (j == 1)      gPhi[t * 512 + tid] = v;
            else if (j == 2) gPhi[t * 512 + 256 + tid] = v;
            else             gH[t * 256 + tid] = v;
        }
        return;
    }

    int bbase = blockIdx.x * 16;
    int ts = (t < tf) ? t : tf;
    if (tid < 128) sF[tid] = gF[ts * 128 + tid];
    sK[tid] = gK[ts * 512 + tid];
    sK[tid + 256] = gK[ts * 512 + 256 + tid];
    if (tid < 128) {
        int i = tid >> 3, j = tid & 7;
        su[tid] = u[(bbase + i) * (TT * UD) + t * UD + j];
    }
    {
        int i = tid >> 5, j = tid & 31;
        sa[tid] = a[(bbase + i) * (TT * AD) + t * AD + j];
        int e = tid + 256;
        i = e >> 5; j = e & 31;
        sa[e] = a[(bbase + i) * (TT * AD) + t * AD + j];
    }
    __syncthreads();

    int bl = tid >> 4, x = tid & 15;
    float s = 0.f;
    #pragma unroll
    for (int j = 0; j < 8; j++) s += sF[x * 8 + j] * su[bl * 8 + j];
    #pragma unroll
    for (int j = 0; j < 32; j++) s += sK[x * 32 + j] * sa[bl * 32 + j];
    gGv[(t * BSZ + bbase + bl) * 16 + x] = s;
}

// ------ G4_t = g_t + P0 g_{t-1} + P1 g_{t-2} + P2 g_{t-3} (P0 = E_t) --------
__global__ void k_g4()
{
    __shared__ float sP0t[256], sP1t[256], sP2t[256], sg[1024];
    __shared__ int stf;
    int tid = threadIdx.x;
    int t = blockIdx.y;
    int bbase = blockIdx.x * 16;
    int r = tid >> 4, c = tid & 15;
    if (tid == 0) stf = gTfreeze;
    __syncthreads();
    int tf = stf;

    sP0t[c * 16 + r] = gE[((t < tf) ? t : tf) * 256 + tid];
    sP1t[c * 16 + r] = gPhi[t * 512 + tid];
    sP2t[c * 16 + r] = gPhi[t * 512 + 256 + tid];
    #pragma unroll
    for (int j = 0; j < 4; j++) {
        int s = t - j;
        sg[j * 256 + tid] = (s >= 0) ? gGv[(s * BSZ + bbase) * 16 + tid] : 0.f;
    }
    __syncthreads();

    int bl = tid >> 4, x = tid & 15;
    float v = sg[bl * 16 + x];
    #pragma unroll
    for (int k = 0; k < 16; k++) v += sP0t[k * 16 + x] * sg[256 + bl * 16 + k];
    #pragma unroll
    for (int k = 0; k < 16; k++) v += sP1t[k * 16 + x] * sg[512 + bl * 16 + k];
    #pragma unroll
    for (int k = 0; k < 16; k++) v += sP2t[k * 16 + x] * sg[768 + bl * 16 + k];
    gG4[(t * BSZ + bbase) * 16 + tid] = v;
}

// ----------- chain: mean_t = H_t mean_{t-4} + G4_t, 4 sub-chains/batch ------
__global__ void k_chain(const float* __restrict__ mean0, float* __restrict__ out)
{
    int tid = threadIdx.x;                  // 256 threads = 16 chains
    int lane = tid & 31, w = tid >> 5;
    int res = blockIdx.x & 3;
    int bbase = (blockIdx.x >> 2) * 16;
    int x = lane & 15;
    int bl = 2 * w + (lane >> 4);
    int b = bbase + bl;

    float mv = mean0[b * 16 + x];

    int t = res;
    const float4* hp = (const float4*)(gH + t * 256 + x * 16);
    float4 h0 = hp[0], h1 = hp[1], h2 = hp[2], h3 = hp[3];
    float gg = gG4[(t * BSZ + b) * 16 + x];

    #pragma unroll 1
    for (int i = 0; i < TT / 4; i++) {
        int tn = t + 4;
        float4 n0, n1, n2, n3; float gn;
        if (tn < TT) {
            const float4* np = (const float4*)(gH + tn * 256 + x * 16);
            n0 = np[0]; n1 = np[1]; n2 = np[2]; n3 = np[3];
            gn = gG4[(tn * BSZ + b) * 16 + x];
        }
        float a0 = gg, a1 = 0.f, a2 = 0.f, a3 = 0.f;
        float hr[16];
        hr[0]=h0.x; hr[1]=h0.y; hr[2]=h0.z; hr[3]=h0.w;
        hr[4]=h1.x; hr[5]=h1.y; hr[6]=h1.z; hr[7]=h1.w;
        hr[8]=h2.x; hr[9]=h2.y; hr[10]=h2.z; hr[11]=h2.w;
        hr[12]=h3.x; hr[13]=h3.y; hr[14]=h3.z; hr[15]=h3.w;
        #pragma unroll
        for (int k = 0; k < 16; k++) {
            float mk = __shfl_sync(0xFFFFFFFFu, mv, k, 16);
            if ((k & 3) == 0)      a0 += hr[k] * mk;
            else if ((k & 3) == 1) a1 += hr[k] * mk;
            else if ((k & 3) == 2) a2 += hr[k] * mk;
            else                   a3 += hr[k] * mk;
        }
        mv = (a0 + a1) + (a2 + a3);
        out[b * (TT * XD) + t * 16 + x] = mv;
        if (tn < TT) { h0 = n0; h1 = n1; h2 = n2; h3 = n3; gg = gn; t = tn; }
    }
}

extern "C" void kernel_launch(void* const* d_in, const int* in_sizes, int n_in,
                              void* d_out, int out_size)
{
    const float* mean0 = (const float*)d_in[0];
    const float* cov0  = (const float*)d_in[1];
    const float* u     = (const float*)d_in[2];
    const float* a     = (const float*)d_in[3];
    const float* Mm    = (const float*)d_in[4];
    const float* Nm    = (const float*)d_in[5];
    const float* dvec  = (const float*)d_in[6];
    const float* Bm    = (const float*)d_in[7];
    const float* Cm    = (const float*)d_in[8];
    const float* nx    = (const float*)d_in[9];
    const float* na    = (const float*)d_in[10];
    float* out = (float*)d_out;

    k_phase1<<<1, 256>>>(cov0, Bm, Mm, Nm, dvec, Cm, nx, na);
    dim3 g2(17, 256);
    k_phase2<<<g2, 256>>>(u, a);
    dim3 g3(16, 256);
    k_g4<<<g3, 256>>>();
    k_chain<<<64, 256>>>(mean0, out);
}

// round 17
// speedup vs baseline: 1.5263x; 1.0882x over previous
#include <cuda_runtime.h>
#include <cuda_bf16.h>

#define XD 16
#define UD 8
#define AD 32
#define TT 256
#define BSZ 256
#define FREEZE_TH 1e-5f

__device__ __align__(256) float gE[TT * XD * XD];
__device__ __align__(256) float gF[TT * XD * UD];
__device__ __align__(256) float gK[TT * XD * AD];
__device__ __align__(256) float gGv[TT * BSZ * XD];
__device__ __align__(256) float gPhi[TT * 2 * 256];   // P1, P2 per t
__device__ __align__(256) float gH[TT * 256];         // P3
__device__ __align__(256) float gG4[TT * BSZ * XD];
__device__ int gTfreeze;

__device__ __forceinline__ float softplusf(float x) {
    return (x > 20.f) ? x : log1pf(expf(x));
}

// ============== phase 1 (fused setup + shared Riccati/gain recursion) =======
__global__ void k_phase1(const float* __restrict__ cov0, const float* __restrict__ Bm,
                         const float* __restrict__ Mm, const float* __restrict__ Nm,
                         const float* __restrict__ dvec, const float* __restrict__ Cm,
                         const float* __restrict__ nx, const float* __restrict__ na)
{
    __shared__ float Qs[256], Us[256], T2[256], sq[16], si[16], rna[32];
    __shared__ float sP[256], sPp[256], sT[256], sM[256], sW[256];
    __shared__ float sA[256], sAT[256], sG[256], sCtNi[512], sY[512], sB[128], sNx[16];
    __shared__ float redmax[8];

    int tid = threadIdx.x;                  // 256 threads
    int r = tid >> 4, c = tid & 15;
    int lane = tid & 31, warp = tid >> 5;

    if (warp < 2 && lane < 16) {            // warp-MGS QR (positive-diag R)
        const float* src = warp ? Nm : Mm;
        float v[16];
        #pragma unroll
        for (int j = 0; j < 16; j++) v[j] = src[lane * 16 + j];
        #pragma unroll 1
        for (int j = 0; j < 16; j++) {
            float s = v[j] * v[j];
            #pragma unroll
            for (int o = 8; o > 0; o >>= 1) s += __shfl_xor_sync(0xFFFFu, s, o);
            float invn = rsqrtf(s);
            v[j] *= invn;
            for (int k = j + 1; k < 16; k++) {
                float dt = v[j] * v[k];
                #pragma unroll
                for (int o = 8; o > 0; o >>= 1) dt += __shfl_xor_sync(0xFFFFu, dt, o);
                v[k] -= dt * v[j];
            }
        }
        float* dst = warp ? Us : Qs;
        #pragma unroll
        for (int j = 0; j < 16; j++) dst[lane * 16 + j] = v[j];
    }
    if (tid < 16) {
        float dsp = softplusf(dvec[tid]);
        sq[tid] = sqrtf(dsp);
        si[tid] = rsqrtf(1.0f + dsp);
        sNx[tid] = softplusf(nx[tid]) + 1e-4f;
    }
    if (tid < 32) rna[tid] = 1.0f / (softplusf(na[tid]) + 1e-4f);
    if (tid < 128) sB[tid] = Bm[tid];
    sP[tid] = cov0[tid];                    // batch 0 (identical across b)
    __syncthreads();

    {   // T2 = diag(sq) Q diag(si) Uq^T
        int k = tid >> 4, j = tid & 15;
        float s = 0.f;
        #pragma unroll
        for (int l = 0; l < 16; l++) s += Qs[k * 16 + l] * si[l] * Us[j * 16 + l];
        T2[tid] = sq[k] * s;
    }
    __syncthreads();
    {   // A = Uq @ T2 ; G = C^T Na^-1 C ; CtNi
        float s = 0.f;
        #pragma unroll
        for (int k = 0; k < 16; k++) s += Us[r * 16 + k] * T2[k * 16 + c];
        sA[tid] = s;
        sAT[c * 16 + r] = s;
        float g = 0.f;
        #pragma unroll
        for (int a2 = 0; a2 < 32; a2++) g += Cm[a2 * 16 + r] * Cm[a2 * 16 + c] * rna[a2];
        sG[tid] = g;
        #pragma unroll
        for (int j = 0; j < 2; j++) {
            int e = tid + j * 256;
            int i = e >> 5, a2 = e & 31;
            sCtNi[e] = Cm[a2 * 16 + i] * rna[a2];
        }
    }
    __syncthreads();

    int tfz = TT - 1;
    for (int t = 0; t < TT; t++) {
        {   // T = A @ P
            float s = 0.f;
            #pragma unroll
            for (int k = 0; k < 16; k++) s += sA[r * 16 + k] * sP[k * 16 + c];
            sT[tid] = s;
        }
        __syncthreads();
        {   // Pp = T @ A^T + diag(Nx)
            float s = 0.f;
            #pragma unroll
            for (int k = 0; k < 16; k++) s += sT[r * 16 + k] * sAT[k * 16 + c];
            if (r == c) s += sNx[r];
            sPp[tid] = s;
        }
        __syncthreads();
        {   // M = I + Pp @ G ; Y = Pp @ CtNi
            float s = 0.f;
            #pragma unroll
            for (int k = 0; k < 16; k++) s += sPp[r * 16 + k] * sG[k * 16 + c];
            if (r == c) s += 1.0f;
            sM[tid] = s;
            #pragma unroll
            for (int j = 0; j < 2; j++) {
                int e = tid + j * 256;
                int ry = e >> 5, ca = e & 31;
                float y = 0.f;
                #pragma unroll
                for (int k = 0; k < 16; k++) y += sPp[ry * 16 + k] * sCtNi[k * 32 + ca];
                sY[e] = y;
            }
        }
        __syncthreads();
        if (tid < 16) {   // W = inv(M), warp-register Gauss-Jordan
            float m[16];
            #pragma unroll
            for (int i = 0; i < 16; i++) m[i] = sM[i * 16 + tid];
            #pragma unroll 1
            for (int k = 0; k < 16; k++) {
                float ipiv = 1.0f / __shfl_sync(0xFFFFu, m[k], k);
                float rk = ((tid == k) ? 1.0f : m[k]) * ipiv;
                m[k] = rk;
                #pragma unroll
                for (int i = 0; i < 16; i++) {
                    float fi = __shfl_sync(0xFFFFu, m[i], k);
                    if (i != k) {
                        float base = (tid == k) ? 0.0f : m[i];
                        m[i] = base - fi * rk;
                    }
                }
            }
            #pragma unroll
            for (int i = 0; i < 16; i++) sW[i * 16 + tid] = m[i];
        }
        __syncthreads();
        {   // Pn = W@Pp ; E = W@A ; F = W@B ; K = W@Y ; delta
            float pn = 0.f, ee = 0.f;
            #pragma unroll
            for (int k = 0; k < 16; k++) {
                float w = sW[r * 16 + k];
                pn += w * sPp[k * 16 + c];
                ee += w * sA[k * 16 + c];
            }
            gE[t * 256 + tid] = ee;
            if (tid < 128) {
                int rf = tid >> 3, cu = tid & 7;
                float f = 0.f;
                #pragma unroll
                for (int k = 0; k < 16; k++) f += sW[rf * 16 + k] * sB[k * 8 + cu];
                gF[t * 128 + tid] = f;
            }
            #pragma unroll
            for (int j = 0; j < 2; j++) {
                int e = tid + j * 256;
                int rk2 = e >> 5, ca = e & 31;
                float kk = 0.f;
                #pragma unroll
                for (int k = 0; k < 16; k++) kk += sW[rk2 * 16 + k] * sY[k * 32 + ca];
                gK[t * 512 + e] = kk;
            }
            float d = fabsf(pn - sP[tid]);
            sP[tid] = pn;
            #pragma unroll
            for (int o = 16; o > 0; o >>= 1)
                d = fmaxf(d, __shfl_xor_sync(0xFFFFFFFFu, d, o));
            if (lane == 0) redmax[warp] = d;
        }
        __syncthreads();
        {
            float m = redmax[0];
            #pragma unroll
            for (int w2 = 1; w2 < 8; w2++) m = fmaxf(m, redmax[w2]);
            if (m < FREEZE_TH) { tfz = t; break; }
        }
    }
    if (tid == 0) gTfreeze = tfz;
}

// ====== phase 2 (g[t,b] = F_t u + K_t a) fused with stride-4 products =======
__global__ void k_phase2(const float* __restrict__ u, const float* __restrict__ a)
{
    __shared__ float sF[128], sK[512], su[128], sa[512];
    __shared__ float sCur[256], sNext[256];
    __shared__ int stf;
    int tid = threadIdx.x;
    int t = blockIdx.y;
    if (tid == 0) stf = gTfreeze;
    __syncthreads();
    int tf = stf;

    if (blockIdx.x == 16) {
        int r = tid >> 4, c = tid & 15;
        sCur[tid] = gE[((t < tf) ? t : tf) * 256 + tid];
        #pragma unroll 1
        for (int j = 1; j <= 3; j++) {
            int s = t - j;
            if (s >= 0) sNext[tid] = gE[((s < tf) ? s : tf) * 256 + tid];
            __syncthreads();
            float v;
            if (s >= 0) {
                v = 0.f;
                #pragma unroll
                for (int k = 0; k < 16; k++) v += sCur[r * 16 + k] * sNext[k * 16 + c];
            } else {
                v = sCur[tid];
            }
            __syncthreads();
            sCur[tid] = v;
            if (j == 1)      gPhi[t * 512 + tid] = v;
            else if (j == 2) gPhi[t * 512 + 256 + tid] = v;
            else             gH[t * 256 + tid] = v;
        }
        return;
    }

    int bbase = blockIdx.x * 16;
    int ts = (t < tf) ? t : tf;
    if (tid < 128) sF[tid] = gF[ts * 128 + tid];
    sK[tid] = gK[ts * 512 + tid];
    sK[tid + 256] = gK[ts * 512 + 256 + tid];
    if (tid < 128) {
        int i = tid >> 3, j = tid & 7;
        su[tid] = u[(bbase + i) * (TT * UD) + t * UD + j];
    }
    {
        int i = tid >> 5, j = tid & 31;
        sa[tid] = a[(bbase + i) * (TT * AD) + t * AD + j];
        int e = tid + 256;
        i = e >> 5; j = e & 31;
        sa[e] = a[(bbase + i) * (TT * AD) + t * AD + j];
    }
    __syncthreads();

    int bl = tid >> 4, x = tid & 15;
    float s = 0.f;
    #pragma unroll
    for (int j = 0; j < 8; j++) s += sF[x * 8 + j] * su[bl * 8 + j];
    #pragma unroll
    for (int j = 0; j < 32; j++) s += sK[x * 32 + j] * sa[bl * 32 + j];
    gGv[(t * BSZ + bbase + bl) * 16 + x] = s;
}

// ------ G4_t = g_t + P0 g_{t-1} + P1 g_{t-2} + P2 g_{t-3} (P0 = E_t) --------
__global__ void k_g4()
{
    __shared__ float sP0t[256], sP1t[256], sP2t[256], sg[1024];
    __shared__ int stf;
    int tid = threadIdx.x;
    int t = blockIdx.y;
    int bbase = blockIdx.x * 16;
    int r = tid >> 4, c = tid & 15;
    if (tid == 0) stf = gTfreeze;
    __syncthreads();
    int tf = stf;

    sP0t[c * 16 + r] = gE[((t < tf) ? t : tf) * 256 + tid];
    sP1t[c * 16 + r] = gPhi[t * 512 + tid];
    sP2t[c * 16 + r] = gPhi[t * 512 + 256 + tid];
    #pragma unroll
    for (int j = 0; j < 4; j++) {
        int s = t - j;
        sg[j * 256 + tid] = (s >= 0) ? gGv[(s * BSZ + bbase) * 16 + tid] : 0.f;
    }
    __syncthreads();

    int bl = tid >> 4, x = tid & 15;
    float v = sg[bl * 16 + x];
    #pragma unroll
    for (int k = 0; k < 16; k++) v += sP0t[k * 16 + x] * sg[256 + bl * 16 + k];
    #pragma unroll
    for (int k = 0; k < 16; k++) v += sP1t[k * 16 + x] * sg[512 + bl * 16 + k];
    #pragma unroll
    for (int k = 0; k < 16; k++) v += sP2t[k * 16 + x] * sg[768 + bl * 16 + k];
    gG4[(t * BSZ + bbase) * 16 + tid] = v;
}

// -------- chain: mean_t = H_t mean_{t-4} + G4_t, smem-staged H, ------------
// -------- register prefetch ring for G4. 64 blocks, 16 chains each. --------
__global__ void k_chain(const float* __restrict__ mean0, float* __restrict__ out)
{
    __shared__ float sH[32 * 256];          // 32 KB: half of this residue's H's
    int tid = threadIdx.x;                  // 256 threads = 16 chains
    int lane = tid & 31, w = tid >> 5;
    int res = blockIdx.x & 3;
    int bbase = (blockIdx.x >> 2) * 16;
    int x = lane & 15;
    int bl = 2 * w + (lane >> 4);
    int b = bbase + bl;

    float mv = mean0[b * 16 + x];

    // G4 prefetch ring, depth 4 (step index s = 0..63, t = res + 4s)
    float gq[4];
    #pragma unroll
    for (int j = 0; j < 4; j++)
        gq[j] = gG4[(((res + 4 * j) * BSZ) + b) * 16 + x];

    #pragma unroll 1
    for (int half = 0; half < 2; half++) {
        if (half) __syncthreads();          // protect sH overwrite
        // stage 32 H matrices (coalesced float4)
        #pragma unroll
        for (int j = 0; j < 8; j++) {
            int idx = tid + j * 256;        // float4 index, 2048 total
            int i = idx >> 6, e = idx & 63;
            int t = res + 4 * (half * 32 + i);
            ((float4*)sH)[idx] = ((const float4*)(gH + t * 256))[e];
        }
        __syncthreads();

        #pragma unroll
        for (int i = 0; i < 32; i++) {
            int s = half * 32 + i;
            float gg = gq[i & 3];           // s&3 == i&3 (half*32 % 4 == 0)
            int sp = s + 4;
            if (sp < 64)
                gq[i & 3] = gG4[(((res + 4 * sp) * BSZ) + b) * 16 + x];

            const float4* hp = (const float4*)(sH + i * 256 + x * 16);
            float4 h0 = hp[0], h1 = hp[1], h2 = hp[2], h3 = hp[3];
            float hr[16];
            hr[0]=h0.x; hr[1]=h0.y; hr[2]=h0.z; hr[3]=h0.w;
            hr[4]=h1.x; hr[5]=h1.y; hr[6]=h1.z; hr[7]=h1.w;
            hr[8]=h2.x; hr[9]=h2.y; hr[10]=h2.z; hr[11]=h2.w;
            hr[12]=h3.x; hr[13]=h3.y; hr[14]=h3.z; hr[15]=h3.w;

            float a0 = gg, a1 = 0.f, a2 = 0.f, a3 = 0.f;
            #pragma unroll
            for (int k = 0; k < 16; k++) {
                float mk = __shfl_sync(0xFFFFFFFFu, mv, k, 16);
                if ((k & 3) == 0)      a0 += hr[k] * mk;
                else if ((k & 3) == 1) a1 += hr[k] * mk;
                else if ((k & 3) == 2) a2 += hr[k] * mk;
                else                   a3 += hr[k] * mk;
            }
            mv = (a0 + a1) + (a2 + a3);
            int t = res + 4 * s;
            out[b * (TT * XD) + t * 16 + x] = mv;
        }
    }
}

extern "C" void kernel_launch(void* const* d_in, const int* in_sizes, int n_in,
                              void* d_out, int out_size)
{
    const float* mean0 = (const float*)d_in[0];
    const float* cov0  = (const float*)d_in[1];
    const float* u     = (const float*)d_in[2];
    const float* a     = (const float*)d_in[3];
    const float* Mm    = (const float*)d_in[4];
    const float* Nm    = (const float*)d_in[5];
    const float* dvec  = (const float*)d_in[6];
    const float* Bm    = (const float*)d_in[7];
    const float* Cm    = (const float*)d_in[8];
    const float* nx    = (const float*)d_in[9];
    const float* na    = (const float*)d_in[10];
    float* out = (float*)d_out;

    k_phase1<<<1, 256>>>(cov0, Bm, Mm, Nm, dvec, Cm, nx, na);
    dim3 g2(17, 256);
    k_phase2<<<g2, 256>>>(u, a);
    dim3 g3(16, 256);
    k_g4<<<g3, 256>>>();
    k_chain<<<64, 256>>>(mean0, out);
}